// round 6
// baseline (speedup 1.0000x reference)
#include <cuda_runtime.h>

typedef unsigned long long ull;

#define BATCH 256
#define NTOK  256
#define NFULL 257
#define DIM   768
#define KC    8
#define VCNT  10000
#define ITERS 4
#define NDP   (DIM/2)       /* 384 packed dim-pairs */
#define BTHREADS 192        /* phase-B threads: each owns 4 dims */

__device__ float g_src[BATCH * KC];   // final centroid scalar c0hat[k][0] per (b,k)
__device__ float g_delta[VCNT];       // scatter-add accumulators per concept row

// ---------------- packed f32x2 helpers (sm_103a) ----------------
__device__ __forceinline__ ull ffma2(ull a, ull b, ull c) {
    ull d; asm("fma.rn.f32x2 %0, %1, %2, %3;" : "=l"(d) : "l"(a), "l"(b), "l"(c)); return d;
}
__device__ __forceinline__ ull fadd2(ull a, ull b) {
    ull d; asm("add.rn.f32x2 %0, %1, %2;" : "=l"(d) : "l"(a), "l"(b)); return d;
}
__device__ __forceinline__ ull pack2(float x, float y) {
    ull r; asm("mov.b64 %0, {%1, %2};" : "=l"(r) : "f"(x), "f"(y)); return r;
}
__device__ __forceinline__ void unpack2(ull v, float& x, float& y) {
    asm("mov.b64 {%0, %1}, %2;" : "=f"(x), "=f"(y) : "l"(v));
}

// =====================================================================
// Kernel 1: per-batch k-means. 1 block per batch, 256 threads.
//   s_diff[dp*8+k] = packed (diff[k][2dp], diff[k][2dp+1]),  diff = c1hat - c0hat
//   s_af2[n*8+k]   = packed (a, a) with a = assign(n,k) in {0,1}
// =====================================================================
__global__ __launch_bounds__(256, 2)
void kmeans_kernel(const float* __restrict__ tokens,
                   const float* __restrict__ vc,
                   const int*   __restrict__ topk,
                   float*       __restrict__ out_assign)
{
    __shared__ __align__(16) ull s_diff[NDP * KC];   // 24 KB
    __shared__ __align__(16) ull s_af2[NTOK * KC];   // 16 KB
    __shared__ float s_part[6][16];
    __shared__ float s_inv[16];

    const int b    = blockIdx.x;
    const int tid  = threadIdx.x;
    const int lane = tid & 31;
    const int w    = tid >> 5;

    const float* tokbase = tokens + ((size_t)b * NFULL + 1) * DIM;

    // ---- token-sum prepass (iteration-invariant). Thread owns dims [4tid,4tid+4).
    ull ts0 = 0ull, ts1 = 0ull;   // bits of (0.f,0.f)
    if (tid < BTHREADS) {
        const float* tp = tokbase + (tid << 2);
        for (int n = 0; n < NTOK; ++n) {
            ulonglong2 t = *(const ulonglong2*)(tp + (size_t)n * DIM);
            ts0 = fadd2(ts0, t.x);
            ts1 = fadd2(ts1, t.y);
        }
    }
    float tsx0, tsx1, tsx2, tsx3;
    unpack2(ts0, tsx0, tsx1);
    unpack2(ts1, tsx2, tsx3);

    // ---- initial diff from l2-normalized gathered concepts. Warp w handles k=w.
    {
        const int k   = w;
        const int idx = topk[b * KC + k];
        const float4* r0 = (const float4*)(vc + (size_t)idx * 2 * DIM);
        const float4* r1 = r0 + DIM / 4;
        float ss0 = 0.f, ss1 = 0.f;
        for (int j = lane; j < DIM / 4; j += 32) {
            float4 a = r0[j]; ss0 += a.x*a.x + a.y*a.y + a.z*a.z + a.w*a.w;
            float4 c = r1[j]; ss1 += c.x*c.x + c.y*c.y + c.z*c.z + c.w*c.w;
        }
        #pragma unroll
        for (int off = 16; off; off >>= 1) {
            ss0 += __shfl_down_sync(0xffffffffu, ss0, off);
            ss1 += __shfl_down_sync(0xffffffffu, ss1, off);
        }
        ss0 = __shfl_sync(0xffffffffu, ss0, 0);
        ss1 = __shfl_sync(0xffffffffu, ss1, 0);
        const float i0 = 1.f / fmaxf(sqrtf(ss0), 1e-12f);
        const float i1 = 1.f / fmaxf(sqrtf(ss1), 1e-12f);
        const float2* p0 = (const float2*)(vc + (size_t)idx * 2 * DIM);
        const float2* p1 = p0 + DIM / 2;
        for (int dp = lane; dp < NDP; dp += 32) {
            float2 a = p0[dp];
            float2 c = p1[dp];
            s_diff[dp * KC + k] = pack2(c.x * i1 - a.x * i0, c.y * i1 - a.y * i0);
        }
    }
    __syncthreads();

    // ================= main k-means loop =================
    for (int it = 0; it < ITERS; ++it) {
        // ---------- Phase A: assignments. Thread owns token n = tid. ----------
        {
            const ulonglong2* trow = (const ulonglong2*)(tokbase + (size_t)tid * DIM);
            const ulonglong2* dq   = (const ulonglong2*)s_diff;
            ull s0 = 0ull, s1 = 0ull, s2 = 0ull, s3 = 0ull,
                s4 = 0ull, s5 = 0ull, s6 = 0ull, s7 = 0ull;
            // 192 iterations x 4 dims = full 768-dim dot (R5 bug: this was 96)
            #pragma unroll 4
            for (int j2 = 0; j2 < 192; ++j2) {
                ulonglong2 t = trow[j2];
                const ulonglong2* d2 = dq + (j2 << 3);
                ulonglong2 p0 = d2[0], p1 = d2[1], p2 = d2[2], p3 = d2[3];
                s0 = ffma2(t.x, p0.x, s0);  s1 = ffma2(t.x, p0.y, s1);
                s2 = ffma2(t.x, p1.x, s2);  s3 = ffma2(t.x, p1.y, s3);
                s4 = ffma2(t.x, p2.x, s4);  s5 = ffma2(t.x, p2.y, s5);
                s6 = ffma2(t.x, p3.x, s6);  s7 = ffma2(t.x, p3.y, s7);
                p0 = d2[4]; p1 = d2[5]; p2 = d2[6]; p3 = d2[7];
                s0 = ffma2(t.y, p0.x, s0);  s1 = ffma2(t.y, p0.y, s1);
                s2 = ffma2(t.y, p1.x, s2);  s3 = ffma2(t.y, p1.y, s3);
                s4 = ffma2(t.y, p2.x, s4);  s5 = ffma2(t.y, p2.y, s5);
                s6 = ffma2(t.y, p3.x, s6);  s7 = ffma2(t.y, p3.y, s7);
            }
            float af[KC];
            {
                float x, y;
                unpack2(s0, x, y); af[0] = (x + y) > 0.f ? 1.f : 0.f;
                unpack2(s1, x, y); af[1] = (x + y) > 0.f ? 1.f : 0.f;
                unpack2(s2, x, y); af[2] = (x + y) > 0.f ? 1.f : 0.f;
                unpack2(s3, x, y); af[3] = (x + y) > 0.f ? 1.f : 0.f;
                unpack2(s4, x, y); af[4] = (x + y) > 0.f ? 1.f : 0.f;
                unpack2(s5, x, y); af[5] = (x + y) > 0.f ? 1.f : 0.f;
                unpack2(s6, x, y); af[6] = (x + y) > 0.f ? 1.f : 0.f;
                unpack2(s7, x, y); af[7] = (x + y) > 0.f ? 1.f : 0.f;
            }
            ull* ap = s_af2 + (tid << 3);
            #pragma unroll
            for (int k = 0; k < KC; ++k) ap[k] = pack2(af[k], af[k]);

            if (it == ITERS - 1) {
                float4* o = (float4*)(out_assign + ((size_t)b * NTOK + tid) * KC);
                o[0] = make_float4(af[0], af[1], af[2], af[3]);
                o[1] = make_float4(af[4], af[5], af[6], af[7]);
            }
        }
        __syncthreads();

        // ---------- Phase B: gated accumulation c1[k][d]. ----------
        // Thread (tid<192) owns dims [4tid,4tid+4); warps iterate tokens in
        // lockstep so assign loads are uniform-address broadcasts.
        ull a0 = 0ull, a1 = 0ull, a2 = 0ull, a3 = 0ull,
            a4 = 0ull, a5 = 0ull, a6 = 0ull, a7 = 0ull,
            a8 = 0ull, a9 = 0ull, a10 = 0ull, a11 = 0ull,
            a12 = 0ull, a13 = 0ull, a14 = 0ull, a15 = 0ull;
        if (tid < BTHREADS) {
            const float* tp = tokbase + (tid << 2);
            #pragma unroll 2
            for (int n = 0; n < NTOK; ++n) {
                ulonglong2 t = *(const ulonglong2*)(tp + (size_t)n * DIM);
                const ulonglong2* q = (const ulonglong2*)(s_af2 + (n << 3));
                ulonglong2 m01 = q[0], m23 = q[1], m45 = q[2], m67 = q[3];
                a0  = ffma2(t.x, m01.x, a0);   a1  = ffma2(t.y, m01.x, a1);
                a2  = ffma2(t.x, m01.y, a2);   a3  = ffma2(t.y, m01.y, a3);
                a4  = ffma2(t.x, m23.x, a4);   a5  = ffma2(t.y, m23.x, a5);
                a6  = ffma2(t.x, m23.y, a6);   a7  = ffma2(t.y, m23.y, a7);
                a8  = ffma2(t.x, m45.x, a8);   a9  = ffma2(t.y, m45.x, a9);
                a10 = ffma2(t.x, m45.y, a10);  a11 = ffma2(t.y, m45.y, a11);
                a12 = ffma2(t.x, m67.x, a12);  a13 = ffma2(t.y, m67.x, a13);
                a14 = ffma2(t.x, m67.y, a14);  a15 = ffma2(t.y, m67.y, a15);
            }
        }

        // ---------- norms: ss1[k], ss0[k] (deterministic tree reduction) ----------
        float ssl[16];
        #pragma unroll
        for (int i = 0; i < 16; ++i) ssl[i] = 0.f;
        if (tid < BTHREADS) {
            #define KNORM(k, ae, ao)                                            \
            {   float x0, x1, x2, x3;                                           \
                unpack2(ae, x0, x1); unpack2(ao, x2, x3);                       \
                ssl[k] = x0*x0 + x1*x1 + x2*x2 + x3*x3;                         \
                float y0 = tsx0 - x0, y1 = tsx1 - x1,                           \
                      y2 = tsx2 - x2, y3 = tsx3 - x3;                           \
                ssl[8 + k] = y0*y0 + y1*y1 + y2*y2 + y3*y3;                     \
            }
            KNORM(0, a0,  a1)   KNORM(1, a2,  a3)
            KNORM(2, a4,  a5)   KNORM(3, a6,  a7)
            KNORM(4, a8,  a9)   KNORM(5, a10, a11)
            KNORM(6, a12, a13)  KNORM(7, a14, a15)
            #undef KNORM
        }
        #pragma unroll
        for (int i = 0; i < 16; ++i) {
            float v = ssl[i];
            #pragma unroll
            for (int off = 16; off; off >>= 1)
                v += __shfl_down_sync(0xffffffffu, v, off);
            if (lane == 0 && w < 6) s_part[w][i] = v;
        }
        __syncthreads();
        if (tid < 16) {
            float v = s_part[0][tid] + s_part[1][tid] + s_part[2][tid]
                    + s_part[3][tid] + s_part[4][tid] + s_part[5][tid];
            s_inv[tid] = 1.f / fmaxf(sqrtf(v), 1e-12f);
        }
        __syncthreads();

        // ---------- write next diff = c1*inv1 - c0*inv0 ----------
        if (tid < BTHREADS) {
            const int dp0 = tid * 2;
            #define KDIFF(k, ae, ao)                                            \
            {   float i1 = s_inv[k], i0 = s_inv[8 + k];                         \
                float x0, x1, x2, x3;                                           \
                unpack2(ae, x0, x1); unpack2(ao, x2, x3);                       \
                float y0 = tsx0 - x0, y1 = tsx1 - x1,                           \
                      y2 = tsx2 - x2, y3 = tsx3 - x3;                           \
                s_diff[dp0 * KC + k]       = pack2(x0*i1 - y0*i0, x1*i1 - y1*i0);\
                s_diff[(dp0 + 1) * KC + k] = pack2(x2*i1 - y2*i0, x3*i1 - y3*i0);\
            }
            KDIFF(0, a0,  a1)   KDIFF(1, a2,  a3)
            KDIFF(2, a4,  a5)   KDIFF(3, a6,  a7)
            KDIFF(4, a8,  a9)   KDIFF(5, a10, a11)
            KDIFF(6, a12, a13)  KDIFF(7, a14, a15)
            #undef KDIFF

            if (it == ITERS - 1 && tid == 0) {
                // final normalized c0hat[k][d=0] scalars feed the scatter
                float x, yy;
                #define KSRC(k, ae)                                             \
                {   unpack2(ae, x, yy);                                         \
                    g_src[b * KC + k] = (tsx0 - x) * s_inv[8 + k];  }
                KSRC(0, a0)  KSRC(1, a2)  KSRC(2, a4)  KSRC(3, a6)
                KSRC(4, a8)  KSRC(5, a10) KSRC(6, a12) KSRC(7, a14)
                #undef KSRC
            }
        }
        __syncthreads();
    }
}

// =====================================================================
// Kernel 2: deterministic scatter of 2048 scalars into g_delta[V].
// Single block; first-occurrence thread owns an index and sums all its
// duplicates in ascending order (no atomics -> bitwise deterministic).
// =====================================================================
__global__ void scatter_kernel(const int* __restrict__ topk)
{
    __shared__ int   sidx[BATCH * KC];
    __shared__ float ssrc[BATCH * KC];
    const int tid = threadIdx.x;
    for (int i = tid; i < BATCH * KC; i += blockDim.x) {
        sidx[i] = topk[i];
        ssrc[i] = g_src[i];
    }
    for (int i = tid; i < VCNT; i += blockDim.x) g_delta[i] = 0.f;
    __syncthreads();
    for (int e = tid; e < BATCH * KC; e += blockDim.x) {
        const int v = sidx[e];
        bool first = true;
        for (int j = 0; j < e; ++j)
            if (sidx[j] == v) { first = false; break; }
        if (first) {
            float s = 0.f;
            for (int j = e; j < BATCH * KC; ++j)
                if (sidx[j] == v) s += ssrc[j];
            g_delta[v] = s;
        }
    }
}

// =====================================================================
// Kernel 3: vc_new = l2norm(visual_concepts with scalar added at [v,0,0]).
// One block per (v,c) row, 192 threads x float4 = 768 floats. HBM-bound.
// =====================================================================
__global__ __launch_bounds__(192)
void vcnew_kernel(const float* __restrict__ vc, float* __restrict__ out)
{
    __shared__ float sp[6];
    __shared__ float s_scale;
    const int r    = blockIdx.x;          // r = v*2 + c
    const int tid  = threadIdx.x;
    const int lane = tid & 31, w = tid >> 5;

    const float4* src = (const float4*)(vc + (size_t)r * DIM);
    float4 v = src[tid];
    if (tid == 0 && (r & 1) == 0) v.x += g_delta[r >> 1];

    float ss = v.x*v.x + v.y*v.y + v.z*v.z + v.w*v.w;
    #pragma unroll
    for (int off = 16; off; off >>= 1)
        ss += __shfl_down_sync(0xffffffffu, ss, off);
    if (lane == 0) sp[w] = ss;
    __syncthreads();
    if (tid == 0) {
        float t = sp[0] + sp[1] + sp[2] + sp[3] + sp[4] + sp[5];
        s_scale = 1.f / fmaxf(sqrtf(t), 1e-12f);
    }
    __syncthreads();
    const float sc = s_scale;
    ((float4*)(out + (size_t)r * DIM))[tid] =
        make_float4(v.x * sc, v.y * sc, v.z * sc, v.w * sc);
}

// =====================================================================
extern "C" void kernel_launch(void* const* d_in, const int* in_sizes, int n_in,
                              void* d_out, int out_size)
{
    // Bind inputs by element count (robust to metadata ordering):
    //   tokens: 256*257*768 = 50,528,256   vc: 10000*2*768 = 15,360,000   topk: 2048
    const float* tokens = nullptr;
    const float* vc     = nullptr;
    const int*   topk   = nullptr;
    for (int i = 0; i < n_in; ++i) {
        if (in_sizes[i] == BATCH * NFULL * DIM)      tokens = (const float*)d_in[i];
        else if (in_sizes[i] == VCNT * 2 * DIM)      vc     = (const float*)d_in[i];
        else if (in_sizes[i] == BATCH * KC)          topk   = (const int*)d_in[i];
    }
    float* out = (float*)d_out;   // [assignments (B,256,8) | vc_new (10000,2,768)]

    kmeans_kernel<<<BATCH, 256>>>(tokens, vc, topk, out);
    scatter_kernel<<<1, 1024>>>(topk);
    vcnew_kernel<<<VCNT * 2, DIM / 4>>>(vc, out + (size_t)BATCH * NTOK * KC);
}

// round 9
// speedup vs baseline: 4.5099x; 4.5099x over previous
#include <cuda_runtime.h>

typedef unsigned long long ull;

#define BATCH 256
#define NTOK  256
#define NFULL 257
#define DIM   768
#define KC    8
#define VCNT  10000
#define ITERS 4

#define CHTOK 32                 /* tokens per smem chunk */
#define NCH   8                  /* chunks per pass (256/32) */
#define TKS   386                /* ull stride per token row (384 dp + 2 pad; 3088B; bank-shift 4 words) */
#define DFS   390                /* ull stride per k row of diff (780 words = 12 mod 32: conflict-free) */
#define BUFULL (CHTOK * TKS)     /* 12352 ull per stage buffer */

/* dynamic smem layout (bytes) */
#define OFF_TK   0
#define SZ_TK    (2 * BUFULL * 8)          /* 197632 : double-buffered token chunks */
#define OFF_DFT  (OFF_TK + SZ_TK)
#define SZ_DFT   (KC * DFS * 8)            /* 24960  : diff[k][dp] */
#define OFF_A2   (OFF_DFT + SZ_DFT)
#define SZ_A2    (CHTOK * KC * 8)          /* 2048   : chunk assignments packed (a,a) */
#define OFF_PART (OFF_A2 + SZ_A2)
#define SZ_PART  (8 * 16 * 4)
#define OFF_INV  (OFF_PART + SZ_PART)
#define KM_SMEM  (OFF_INV + 64)            /* 225216 B < 227KB cap */

__device__ float g_src[BATCH * KC];   // final c0hat[k][0] per (b,k)
__device__ float g_delta[VCNT];       // per-concept scatter sums
__device__ int   g_owner[VCNT];       // min element index per concept (deterministic)

// ---------------- packed f32x2 helpers (sm_103a) ----------------
__device__ __forceinline__ ull ffma2(ull a, ull b, ull c) {
    ull d; asm("fma.rn.f32x2 %0, %1, %2, %3;" : "=l"(d) : "l"(a), "l"(b), "l"(c)); return d;
}
__device__ __forceinline__ ull fadd2(ull a, ull b) {
    ull d; asm("add.rn.f32x2 %0, %1, %2;" : "=l"(d) : "l"(a), "l"(b)); return d;
}
__device__ __forceinline__ ull pack2(float x, float y) {
    ull r; asm("mov.b64 %0, {%1, %2};" : "=l"(r) : "f"(x), "f"(y)); return r;
}
__device__ __forceinline__ void unpack2(ull v, float& x, float& y) {
    asm("mov.b64 {%0, %1}, %2;" : "=f"(x), "=f"(y) : "l"(v));
}

// coalesced cp.async stage of one 32-token chunk (32 x 768 floats)
__device__ __forceinline__ void stage_chunk(ull* dstbuf, const float* src, int tid) {
    #pragma unroll
    for (int i = 0; i < 24; ++i) {
        int f = tid + 256 * i;            // 0..6143 16B-segments
        int r = f / 192;                  // token row 0..31
        int s = f - r * 192;              // segment within row
        unsigned d = (unsigned)__cvta_generic_to_shared(dstbuf + r * TKS + s * 2);
        asm volatile("cp.async.cg.shared.global [%0], [%1], 16;"
                     :: "r"(d), "l"(src + (size_t)r * DIM + s * 4));
    }
}

// =====================================================================
// Kernel 1: fused per-batch k-means. One token pass per iteration.
// 1 block/batch, 256 threads, ~220KB dyn smem -> 1 block/SM.
// =====================================================================
__global__ void __launch_bounds__(256, 1)
kmeans_kernel(const float* __restrict__ tokens,
              const float* __restrict__ vc,
              const int*   __restrict__ topk,
              float*       __restrict__ out_assign)
{
    extern __shared__ __align__(16) char smem[];
    ull*   s_tk  = (ull*)(smem + OFF_TK);
    ull*   s_dfT = (ull*)(smem + OFF_DFT);
    ull*   s_a2  = (ull*)(smem + OFF_A2);
    float (*s_part)[16] = (float(*)[16])(smem + OFF_PART);
    float* s_inv = (float*)(smem + OFF_INV);

    const int b    = blockIdx.x;
    const int tid  = threadIdx.x;
    const int lane = tid & 31;
    const int w    = tid >> 5;

    const float* tokbase = tokens + ((size_t)b * NFULL + 1) * DIM;

    // prefetch chunk 0 while building the initial diff matrix
    stage_chunk(s_tk, tokbase, tid);
    asm volatile("cp.async.commit_group;");

    // initial diff = c1hat - c0hat from gathered, l2-normalized concepts (warp w -> k=w)
    {
        const int k   = w;
        const int idx = topk[b * KC + k];
        const float4* r0 = (const float4*)(vc + (size_t)idx * 2 * DIM);
        const float4* r1 = r0 + DIM / 4;
        float ss0 = 0.f, ss1 = 0.f;
        for (int j = lane; j < DIM / 4; j += 32) {
            float4 a = r0[j]; ss0 += a.x*a.x + a.y*a.y + a.z*a.z + a.w*a.w;
            float4 c = r1[j]; ss1 += c.x*c.x + c.y*c.y + c.z*c.z + c.w*c.w;
        }
        #pragma unroll
        for (int off = 16; off; off >>= 1) {
            ss0 += __shfl_down_sync(0xffffffffu, ss0, off);
            ss1 += __shfl_down_sync(0xffffffffu, ss1, off);
        }
        ss0 = __shfl_sync(0xffffffffu, ss0, 0);
        ss1 = __shfl_sync(0xffffffffu, ss1, 0);
        const float i0 = 1.f / fmaxf(sqrtf(ss0), 1e-12f);
        const float i1 = 1.f / fmaxf(sqrtf(ss1), 1e-12f);
        const float2* p0 = (const float2*)(vc + (size_t)idx * 2 * DIM);
        const float2* p1 = p0 + DIM / 2;
        for (int dp = lane; dp < DIM / 2; dp += 32) {
            float2 a = p0[dp];
            float2 c = p1[dp];
            s_dfT[k * DFS + dp] = pack2(c.x * i1 - a.x * i0, c.y * i1 - a.y * i0);
        }
    }
    __syncthreads();

    ull tsA = 0ull, tsB = 0ull;     // tokensum, folded into iter-0 phase B
    float tsx0 = 0.f, tsx1 = 0.f, tsx2 = 0.f, tsx3 = 0.f;

    for (int it = 0; it < ITERS; ++it) {
        ull a0=0,a1=0,a2=0,a3=0,a4=0,a5=0,a6=0,a7=0,
            a8=0,a9=0,a10=0,a11=0,a12=0,a13=0,a14=0,a15=0;

        for (int c = 0; c < NCH; ++c) {
            const bool more = (c < NCH - 1) || (it < ITERS - 1);
            if (more) {
                const int nc = (c + 1) & 7;
                stage_chunk(s_tk + ((c + 1) & 1) * BUFULL,
                            tokbase + (size_t)nc * CHTOK * DIM, tid);
                asm volatile("cp.async.commit_group;");
                asm volatile("cp.async.wait_group 1;");
            } else {
                asm volatile("cp.async.wait_group 0;");
            }
            __syncthreads();

            const ull* buf = s_tk + (c & 1) * BUFULL;

            // ---------- Phase A: thread = (token = tid>>3, k = tid&7) ----------
            {
                const ulonglong2* tkrow = (const ulonglong2*)(buf + (tid >> 3) * TKS);
                const ulonglong2* dfrow = (const ulonglong2*)(s_dfT + (tid & 7) * DFS);
                ull acc0 = 0ull, acc1 = 0ull;
                #pragma unroll 8
                for (int j = 0; j < 192; ++j) {
                    ulonglong2 tv = tkrow[j];
                    ulonglong2 dv = dfrow[j];
                    acc0 = ffma2(tv.x, dv.x, acc0);
                    acc1 = ffma2(tv.y, dv.y, acc1);
                }
                float x0, x1, y0, y1;
                unpack2(acc0, x0, x1); unpack2(acc1, y0, y1);
                const float af = ((x0 + x1) + (y0 + y1)) > 0.f ? 1.f : 0.f;
                s_a2[(tid >> 3) * KC + (tid & 7)] = pack2(af, af);
                if (it == ITERS - 1)
                    out_assign[((size_t)b * NTOK + c * CHTOK + (tid >> 3)) * KC + (tid & 7)] = af;
            }
            __syncthreads();

            // ---------- Phase B: thread (tid<192) owns dims [4tid,4tid+4) ----------
            if (tid < 192) {
                const ull* bb = buf + 2 * tid;
                #pragma unroll 2
                for (int n = 0; n < CHTOK; ++n) {
                    ulonglong2 t = *(const ulonglong2*)(bb + n * TKS);
                    const ulonglong2* q = (const ulonglong2*)(s_a2 + n * KC);
                    ulonglong2 m01 = q[0], m23 = q[1], m45 = q[2], m67 = q[3];
                    a0  = ffma2(t.x, m01.x, a0);   a1  = ffma2(t.y, m01.x, a1);
                    a2  = ffma2(t.x, m01.y, a2);   a3  = ffma2(t.y, m01.y, a3);
                    a4  = ffma2(t.x, m23.x, a4);   a5  = ffma2(t.y, m23.x, a5);
                    a6  = ffma2(t.x, m23.y, a6);   a7  = ffma2(t.y, m23.y, a7);
                    a8  = ffma2(t.x, m45.x, a8);   a9  = ffma2(t.y, m45.x, a9);
                    a10 = ffma2(t.x, m45.y, a10);  a11 = ffma2(t.y, m45.y, a11);
                    a12 = ffma2(t.x, m67.x, a12);  a13 = ffma2(t.y, m67.x, a13);
                    a14 = ffma2(t.x, m67.y, a14);  a15 = ffma2(t.y, m67.y, a15);
                    if (it == 0) { tsA = fadd2(tsA, t.x); tsB = fadd2(tsB, t.y); }
                }
            }
            __syncthreads();
        }

        if (it == 0) { unpack2(tsA, tsx0, tsx1); unpack2(tsB, tsx2, tsx3); }

        // ---------- norms (deterministic tree reduction over 192 dim-owners) ----------
        float ssl[16];
        #pragma unroll
        for (int i = 0; i < 16; ++i) ssl[i] = 0.f;
        if (tid < 192) {
            #define KNORM(k, ae, ao)                                            \
            {   float x0, x1, x2, x3;                                           \
                unpack2(ae, x0, x1); unpack2(ao, x2, x3);                       \
                ssl[k] = x0*x0 + x1*x1 + x2*x2 + x3*x3;                         \
                float y0 = tsx0 - x0, y1 = tsx1 - x1,                           \
                      y2 = tsx2 - x2, y3 = tsx3 - x3;                           \
                ssl[8 + k] = y0*y0 + y1*y1 + y2*y2 + y3*y3;                     \
            }
            KNORM(0, a0,  a1)   KNORM(1, a2,  a3)
            KNORM(2, a4,  a5)   KNORM(3, a6,  a7)
            KNORM(4, a8,  a9)   KNORM(5, a10, a11)
            KNORM(6, a12, a13)  KNORM(7, a14, a15)
            #undef KNORM
        }
        #pragma unroll
        for (int i = 0; i < 16; ++i) {
            float v = ssl[i];
            #pragma unroll
            for (int off = 16; off; off >>= 1)
                v += __shfl_down_sync(0xffffffffu, v, off);
            if (lane == 0) s_part[w][i] = v;
        }
        __syncthreads();
        if (tid < 16) {
            float v = s_part[0][tid] + s_part[1][tid] + s_part[2][tid] + s_part[3][tid]
                    + s_part[4][tid] + s_part[5][tid] + s_part[6][tid] + s_part[7][tid];
            s_inv[tid] = 1.f / fmaxf(sqrtf(v), 1e-12f);
        }
        __syncthreads();

        // ---------- next diff = c1*inv1 - c0*inv0 ----------
        if (tid < 192) {
            const int dp0 = tid * 2;
            #define KDIFF(k, ae, ao)                                            \
            {   float i1 = s_inv[k], i0 = s_inv[8 + k];                         \
                float x0, x1, x2, x3;                                           \
                unpack2(ae, x0, x1); unpack2(ao, x2, x3);                       \
                float y0 = tsx0 - x0, y1 = tsx1 - x1,                           \
                      y2 = tsx2 - x2, y3 = tsx3 - x3;                           \
                s_dfT[k * DFS + dp0]     = pack2(x0*i1 - y0*i0, x1*i1 - y1*i0); \
                s_dfT[k * DFS + dp0 + 1] = pack2(x2*i1 - y2*i0, x3*i1 - y3*i0); \
            }
            KDIFF(0, a0,  a1)   KDIFF(1, a2,  a3)
            KDIFF(2, a4,  a5)   KDIFF(3, a6,  a7)
            KDIFF(4, a8,  a9)   KDIFF(5, a10, a11)
            KDIFF(6, a12, a13)  KDIFF(7, a14, a15)
            #undef KDIFF

            if (it == ITERS - 1 && tid == 0) {
                float x, yy;
                #define KSRC(k, ae)                                             \
                {   unpack2(ae, x, yy);                                         \
                    g_src[b * KC + k] = (tsx0 - x) * s_inv[8 + k];  }
                KSRC(0, a0)  KSRC(1, a2)  KSRC(2, a4)  KSRC(3, a6)
                KSRC(4, a8)  KSRC(5, a10) KSRC(6, a12) KSRC(7, a14)
                #undef KSRC
            }
        }
        __syncthreads();
    }
}

// =====================================================================
// Scatter: deterministic O(n) three-step.
// =====================================================================
__global__ void zero_kernel()
{
    int i = blockIdx.x * blockDim.x + threadIdx.x;
    if (i < VCNT) { g_delta[i] = 0.f; g_owner[i] = 0x7fffffff; }
}
__global__ void own_kernel(const int* __restrict__ topk)
{
    int e = blockIdx.x * blockDim.x + threadIdx.x;
    if (e < BATCH * KC) atomicMin(&g_owner[topk[e]], e);   // int min: order-independent
}
__global__ void sum_kernel(const int* __restrict__ topk)
{
    int e = blockIdx.x * blockDim.x + threadIdx.x;
    if (e >= BATCH * KC) return;
    const int v = topk[e];
    if (g_owner[v] != e) return;                            // owner = first occurrence
    float s = 0.f;
    for (int j = e; j < BATCH * KC; ++j)                    // ascending order: deterministic
        if (topk[j] == v) s += g_src[j];
    g_delta[v] = s;
}

// =====================================================================
// vc_new = l2norm(vc with g_delta[v] added at [v,0,0]). HBM-bound.
// =====================================================================
__global__ __launch_bounds__(192)
void vcnew_kernel(const float* __restrict__ vc, float* __restrict__ out)
{
    __shared__ float sp[6];
    __shared__ float s_scale;
    const int r    = blockIdx.x;          // r = v*2 + c
    const int tid  = threadIdx.x;
    const int lane = tid & 31, w = tid >> 5;

    float4 v = ((const float4*)(vc + (size_t)r * DIM))[tid];
    if (tid == 0 && (r & 1) == 0) v.x += g_delta[r >> 1];

    float ss = v.x*v.x + v.y*v.y + v.z*v.z + v.w*v.w;
    #pragma unroll
    for (int off = 16; off; off >>= 1)
        ss += __shfl_down_sync(0xffffffffu, ss, off);
    if (lane == 0) sp[w] = ss;
    __syncthreads();
    if (tid == 0) {
        float t = sp[0] + sp[1] + sp[2] + sp[3] + sp[4] + sp[5];
        s_scale = 1.f / fmaxf(sqrtf(t), 1e-12f);
    }
    __syncthreads();
    const float sc = s_scale;
    ((float4*)(out + (size_t)r * DIM))[tid] =
        make_float4(v.x * sc, v.y * sc, v.z * sc, v.w * sc);
}

// =====================================================================
extern "C" void kernel_launch(void* const* d_in, const int* in_sizes, int n_in,
                              void* d_out, int out_size)
{
    const float* tokens = nullptr;
    const float* vc     = nullptr;
    const int*   topk   = nullptr;
    for (int i = 0; i < n_in; ++i) {
        if (in_sizes[i] == BATCH * NFULL * DIM)      tokens = (const float*)d_in[i];
        else if (in_sizes[i] == VCNT * 2 * DIM)      vc     = (const float*)d_in[i];
        else if (in_sizes[i] == BATCH * KC)          topk   = (const int*)d_in[i];
    }
    float* out = (float*)d_out;   // [assignments (256,256,8) | vc_new (10000,2,768)]

    static bool attr_set = false;
    if (!attr_set) {
        cudaFuncSetAttribute(kmeans_kernel,
                             cudaFuncAttributeMaxDynamicSharedMemorySize, KM_SMEM);
        attr_set = true;
    }

    kmeans_kernel<<<BATCH, 256, KM_SMEM>>>(tokens, vc, topk, out);
    zero_kernel<<<(VCNT + 255) / 256, 256>>>();
    own_kernel<<<(BATCH * KC + 255) / 256, 256>>>(topk);
    sum_kernel<<<(BATCH * KC + 255) / 256, 256>>>(topk);
    vcnew_kernel<<<VCNT * 2, DIM / 4>>>(vc, out + (size_t)BATCH * NTOK * KC);
}